// round 2
// baseline (speedup 1.0000x reference)
#include <cuda_runtime.h>
#include <cuda_bf16.h>

#define Bn 128
#define Vn 1024
#define Tn 1024
#define Cn 1024
#define VT 16   // v-columns per CTA in the attention kernel

// Scratch (allocation-free rule: __device__ globals)
__device__ float g_vs[Bn * Tn];   // visual_score, atomically accumulated (zeroed each launch)
__device__ float g_ts[Bn * Vn];   // text_score, written exactly once
__device__ float g_acc[Bn * Cn];  // GEMM split-K accumulator (zeroed each launch)

__device__ __forceinline__ float frcp_approx(float x) {
    float r;
    asm("rcp.approx.f32 %0, %1;" : "=f"(r) : "f"(x));
    return r;
}

__device__ __forceinline__ float fex2_approx(float x) {
    float r;
    asm("ex2.approx.f32 %0, %1;" : "=f"(r) : "f"(x));
    return r;
}

// ---------------------------------------------------------------------------
// Kernel 1: fused scores/tanh/softmax/reductions.
// Grid: (Vn/VT, Bn). Block: 256 threads (8 warps, 2 v-columns per warp).
// Pass 1: e = exp(tanh(s)) stored to SMEM; Z_v and text numerator accumulated.
// Pass 2: visual partials from SMEM e, atomicAdd into g_vs.
// ---------------------------------------------------------------------------
extern __shared__ float smem_dyn[];

__global__ __launch_bounds__(256, 3) void attn_pass_kernel(
    const float* __restrict__ vis,     // [B, V]
    const float* __restrict__ txt,     // [B, T]
    const float* __restrict__ w_vis,   // [T]
    const float* __restrict__ w_text,  // [V]
    const float* __restrict__ bias)    // [V]
{
    float* e  = smem_dyn;            // VT * Tn
    float* wv = e + VT * Tn;         // Tn
    float* yt = wv + Tn;             // Tn
    float* g  = yt + Tn;             // VT  (x_v / Z_v)

    const int b   = blockIdx.y;
    const int v0  = blockIdx.x * VT;
    const int tid = threadIdx.x;

    for (int i = tid; i < Tn; i += 256) {
        wv[i] = w_vis[i];
        yt[i] = txt[b * Tn + i];
    }
    __syncthreads();

    const int warp = tid >> 5;
    const int lane = tid & 31;
    const int vl   = warp * 2;  // local v base for this warp

    const float L2E     = 1.4426950408889634f;   // log2(e)
    const float TWO_L2E = 2.8853900817779268f;   // 2*log2(e)

    float x[2], x2[2], c2[2], b2[2];
    float Z[2]    = {0.f, 0.f};
    float Nacc[2] = {0.f, 0.f};

#pragma unroll
    for (int j = 0; j < 2; j++) {
        int vg = v0 + vl + j;
        x[j]  = vis[b * Vn + vg];
        x2[j] = x[j] * TWO_L2E;
        c2[j] = w_text[vg] * TWO_L2E;
        b2[j] = bias[vg] * TWO_L2E;
    }

    // Main loop over T. exp(2s) via ex2, tanh = (t1-1)/(t1+1), E = exp(tanh).
#pragma unroll 4
    for (int i = 0; i < 32; i++) {
        int t = lane + 32 * i;
        float w = wv[t];
        float y = yt[t];
#pragma unroll
        for (int j = 0; j < 2; j++) {
            float s2 = fmaf(x2[j], w, fmaf(y, c2[j], b2[j]));  // 2s*log2e
            float t1 = fex2_approx(s2);                        // exp(2s)
            float r  = frcp_approx(t1 + 1.0f);
            float m  = fmaf(t1, L2E, -L2E);                    // (t1-1)*log2e
            float E  = fex2_approx(m * r);                     // exp(tanh(s))
            e[(vl + j) * Tn + t] = E;
            Z[j] += E;
            Nacc[j] = fmaf(E, y, Nacc[j]);
        }
    }

    // Warp reductions for Z and the text numerator
#pragma unroll
    for (int j = 0; j < 2; j++) {
#pragma unroll
        for (int o = 16; o > 0; o >>= 1) {
            Z[j]    += __shfl_xor_sync(0xffffffffu, Z[j], o);
            Nacc[j] += __shfl_xor_sync(0xffffffffu, Nacc[j], o);
        }
    }

    if (lane == 0) {
#pragma unroll
        for (int j = 0; j < 2; j++) {
            float invZ = 1.0f / Z[j];  // IEEE div, once per column
            g_ts[b * Vn + v0 + vl + j] = Nacc[j] * invZ;
            g[vl + j] = x[j] * invZ;
        }
    }
    __syncthreads();

    // Pass 2: visual partial per t, FMA-only from SMEM
#pragma unroll
    for (int i = 0; i < 4; i++) {
        int t = tid + 256 * i;
        float acc = 0.f;
#pragma unroll
        for (int vv = 0; vv < VT; vv++)
            acc = fmaf(e[vv * Tn + t], g[vv], acc);
        atomicAdd(&g_vs[b * Tn + t], acc);
    }
}

// ---------------------------------------------------------------------------
// Kernel 2: split-K GEMM  out_acc[b,c] += sum_k A[b,k] * W[c,k]
// A = g_vs with W_fv (k-slices 0..3), A = g_ts with W_ft (k-slices 4..7).
// Grid: (16 c-tiles, 8 k-slices). Block 256. CTA tile 128b x 64c, K=256/CTA.
// ---------------------------------------------------------------------------
#define KC 32

__global__ __launch_bounds__(256, 1) void gemm_split_kernel(
    const float* __restrict__ Wfv,  // [C, T]
    const float* __restrict__ Wft)  // [C, V]
{
    __shared__ float As[KC][128];
    __shared__ float Ws[KC][64];

    const int ctile = blockIdx.x;
    const int ks    = blockIdx.y;

    const float* A;
    const float* W;
    int k0;
    if (ks < 4) { A = g_vs; W = Wfv; k0 = ks * 256; }
    else        { A = g_ts; W = Wft; k0 = (ks - 4) * 256; }

    const int c0  = ctile * 64;
    const int tid = threadIdx.x;
    const int tx  = tid & 15;   // c group (4 columns)
    const int ty  = tid >> 4;   // b group (8 rows)

    float acc[8][4];
#pragma unroll
    for (int i = 0; i < 8; i++)
#pragma unroll
        for (int j = 0; j < 4; j++) acc[i][j] = 0.f;

    const int lb = tid >> 1;          // 0..127 (b row for A load)
    const int lk = (tid & 1) * 16;    // 0 or 16
    const int wc = tid >> 2;          // 0..63 (c row for W load)
    const int wk = (tid & 3) * 8;     // 0,8,16,24

    for (int kc = 0; kc < 256; kc += KC) {
        const float4* ap = (const float4*)(A + lb * Tn + k0 + kc + lk);
#pragma unroll
        for (int q = 0; q < 4; q++) {
            float4 v = ap[q];
            As[lk + q * 4 + 0][lb] = v.x;
            As[lk + q * 4 + 1][lb] = v.y;
            As[lk + q * 4 + 2][lb] = v.z;
            As[lk + q * 4 + 3][lb] = v.w;
        }
        const float4* wp = (const float4*)(W + (c0 + wc) * Tn + k0 + kc + wk);
#pragma unroll
        for (int q = 0; q < 2; q++) {
            float4 v = wp[q];
            Ws[wk + q * 4 + 0][wc] = v.x;
            Ws[wk + q * 4 + 1][wc] = v.y;
            Ws[wk + q * 4 + 2][wc] = v.z;
            Ws[wk + q * 4 + 3][wc] = v.w;
        }
        __syncthreads();

#pragma unroll
        for (int kk = 0; kk < KC; kk++) {
            float a[8], wr[4];
            *(float4*)&a[0] = *(const float4*)&As[kk][ty * 8];
            *(float4*)&a[4] = *(const float4*)&As[kk][ty * 8 + 4];
            *(float4*)&wr[0] = *(const float4*)&Ws[kk][tx * 4];
#pragma unroll
            for (int i = 0; i < 8; i++)
#pragma unroll
                for (int j = 0; j < 4; j++)
                    acc[i][j] = fmaf(a[i], wr[j], acc[i][j]);
        }
        __syncthreads();
    }

#pragma unroll
    for (int i = 0; i < 8; i++) {
        int bb = ty * 8 + i;
#pragma unroll
        for (int j = 0; j < 4; j++)
            atomicAdd(&g_acc[bb * Cn + c0 + tx * 4 + j], acc[i][j]);
    }
}

// ---------------------------------------------------------------------------
// Kernel 3: bias + relu epilogue
// ---------------------------------------------------------------------------
__global__ __launch_bounds__(256) void epilogue_kernel(
    const float* __restrict__ bfv,
    const float* __restrict__ bft,
    float* __restrict__ out)
{
    int i = blockIdx.x * 256 + threadIdx.x;
    int c = i & (Cn - 1);
    float v = g_acc[i] + bfv[c] + bft[c];
    out[i] = v > 0.f ? v : 0.f;
}

// ---------------------------------------------------------------------------
extern "C" void kernel_launch(void* const* d_in, const int* in_sizes, int n_in,
                              void* d_out, int out_size)
{
    const float* vis    = (const float*)d_in[0];
    const float* txt    = (const float*)d_in[1];
    const float* w_vis  = (const float*)d_in[2];
    const float* w_text = (const float*)d_in[3];
    const float* bias   = (const float*)d_in[4];
    const float* Wfv    = (const float*)d_in[5];
    const float* bfv    = (const float*)d_in[6];
    const float* Wft    = (const float*)d_in[7];
    const float* bft    = (const float*)d_in[8];
    float* out = (float*)d_out;

    void* vs_ptr = nullptr;
    void* acc_ptr = nullptr;
    cudaGetSymbolAddress(&vs_ptr, g_vs);
    cudaGetSymbolAddress(&acc_ptr, g_acc);
    cudaMemsetAsync(vs_ptr, 0, Bn * Tn * sizeof(float));
    cudaMemsetAsync(acc_ptr, 0, Bn * Cn * sizeof(float));

    const int smem_bytes = (VT * Tn + Tn + Tn + VT) * (int)sizeof(float);  // 73792
    cudaFuncSetAttribute(attn_pass_kernel,
                         cudaFuncAttributeMaxDynamicSharedMemorySize, smem_bytes);

    dim3 g1(Vn / VT, Bn);
    attn_pass_kernel<<<g1, 256, smem_bytes>>>(vis, txt, w_vis, w_text, bias);

    dim3 g2(16, 8);
    gemm_split_kernel<<<g2, 256>>>(Wfv, Wft);

    epilogue_kernel<<<(Bn * Cn) / 256, 256>>>(bfv, bft, out);
}

// round 3
// speedup vs baseline: 1.2452x; 1.2452x over previous
#include <cuda_runtime.h>
#include <cuda_bf16.h>

#define Bn 128
#define Vn 1024
#define Tn 1024
#define Cn 1024
#define VT 16   // v-columns per CTA in the attention kernel

// Scratch (allocation-free rule: __device__ globals)
__device__ float g_vs[Bn * Tn];   // visual_score, atomically accumulated (zeroed each launch)
__device__ float g_ts[Bn * Vn];   // text_score, written exactly once
__device__ float g_acc[Bn * Cn];  // GEMM split-K accumulator (zeroed each launch)

__device__ __forceinline__ float fex2_approx(float x) {
    float r;
    asm("ex2.approx.f32 %0, %1;" : "=f"(r) : "f"(x));
    return r;
}

__device__ __forceinline__ float ftanh_approx(float x) {
    float r;
    asm("tanh.approx.f32 %0, %1;" : "=f"(r) : "f"(x));
    return r;
}

// ---------------------------------------------------------------------------
// Kernel 1: fused scores/tanh/softmax/reductions.
// Grid: (Vn/VT, Bn). Block: 256 threads (8 warps, 2 v-columns per warp).
// Pass 1: E = exp(tanh(s)) stored to SMEM; Z_v and text numerator accumulated.
// Pass 2: visual partials from SMEM E, atomicAdd into g_vs.
// ---------------------------------------------------------------------------
extern __shared__ float smem_dyn[];

__global__ __launch_bounds__(256, 3) void attn_pass_kernel(
    const float* __restrict__ vis,     // [B, V]
    const float* __restrict__ txt,     // [B, T]
    const float* __restrict__ w_vis,   // [T]
    const float* __restrict__ w_text,  // [V]
    const float* __restrict__ bias)    // [V]
{
    float* e  = smem_dyn;            // VT * Tn
    float* wv = e + VT * Tn;         // Tn
    float* yt = wv + Tn;             // Tn
    float* g  = yt + Tn;             // VT  (x_v / Z_v)

    const int b   = blockIdx.y;
    const int v0  = blockIdx.x * VT;
    const int tid = threadIdx.x;

    for (int i = tid; i < Tn; i += 256) {
        wv[i] = w_vis[i];
        yt[i] = txt[b * Tn + i];
    }
    __syncthreads();

    const int warp = tid >> 5;
    const int lane = tid & 31;
    const int vl   = warp * 2;  // local v base for this warp

    const float L2E = 1.4426950408889634f;   // log2(e)

    float x0, x1, c0, c1, bv0, bv1;
    {
        int vg = v0 + vl;
        x0  = vis[b * Vn + vg];
        x1  = vis[b * Vn + vg + 1];
        c0  = w_text[vg];
        c1  = w_text[vg + 1];
        bv0 = bias[vg];
        bv1 = bias[vg + 1];
    }

    float Z0 = 0.f, Z1 = 0.f, N0 = 0.f, N1 = 0.f;

    float* ep0 = e + vl * Tn;
    float* ep1 = ep0 + Tn;

    // Main loop over T. s = x*w + y*c + bias; E = exp(tanh(s)).
#pragma unroll 4
    for (int i = 0; i < 32; i++) {
        int t = lane + 32 * i;
        float w = wv[t];
        float y = yt[t];

        float s0 = fmaf(x0, w, fmaf(y, c0, bv0));
        float s1 = fmaf(x1, w, fmaf(y, c1, bv1));
        float E0 = fex2_approx(ftanh_approx(s0) * L2E);
        float E1 = fex2_approx(ftanh_approx(s1) * L2E);
        ep0[t] = E0;
        ep1[t] = E1;
        Z0 += E0;
        Z1 += E1;
        N0 = fmaf(E0, y, N0);
        N1 = fmaf(E1, y, N1);
    }

    // Warp reductions for Z and the text numerator
#pragma unroll
    for (int o = 16; o > 0; o >>= 1) {
        Z0 += __shfl_xor_sync(0xffffffffu, Z0, o);
        Z1 += __shfl_xor_sync(0xffffffffu, Z1, o);
        N0 += __shfl_xor_sync(0xffffffffu, N0, o);
        N1 += __shfl_xor_sync(0xffffffffu, N1, o);
    }

    if (lane == 0) {
        float iZ0 = 1.0f / Z0;
        float iZ1 = 1.0f / Z1;
        g_ts[b * Vn + v0 + vl]     = N0 * iZ0;
        g_ts[b * Vn + v0 + vl + 1] = N1 * iZ1;
        g[vl]     = x0 * iZ0;
        g[vl + 1] = x1 * iZ1;
    }
    __syncthreads();

    // Pass 2: visual partial per t, FMA-only from SMEM
#pragma unroll
    for (int i = 0; i < 4; i++) {
        int t = tid + 256 * i;
        float acc = 0.f;
#pragma unroll
        for (int vv = 0; vv < VT; vv++)
            acc = fmaf(e[vv * Tn + t], g[vv], acc);
        atomicAdd(&g_vs[b * Tn + t], acc);
    }
}

// ---------------------------------------------------------------------------
// Kernel 2: split-K GEMM  out_acc[b,c] += sum_k A[b,k] * W[c,k]
// A = g_vs with W_fv (k-slices 0..3), A = g_ts with W_ft (k-slices 4..7).
// Grid: (16 c-tiles, 8 k-slices). Block 256. CTA tile 128b x 64c, K=256/CTA.
// ---------------------------------------------------------------------------
#define KC 32

__global__ __launch_bounds__(256, 1) void gemm_split_kernel(
    const float* __restrict__ Wfv,  // [C, T]
    const float* __restrict__ Wft)  // [C, V]
{
    __shared__ float As[KC][128];
    __shared__ float Ws[KC][64];

    const int ctile = blockIdx.x;
    const int ks    = blockIdx.y;

    const float* A;
    const float* W;
    int k0;
    if (ks < 4) { A = g_vs; W = Wfv; k0 = ks * 256; }
    else        { A = g_ts; W = Wft; k0 = (ks - 4) * 256; }

    const int c0  = ctile * 64;
    const int tid = threadIdx.x;
    const int tx  = tid & 15;   // c group (4 columns)
    const int ty  = tid >> 4;   // b group (8 rows)

    float acc[8][4];
#pragma unroll
    for (int i = 0; i < 8; i++)
#pragma unroll
        for (int j = 0; j < 4; j++) acc[i][j] = 0.f;

    const int lb = tid >> 1;          // 0..127 (b row for A load)
    const int lk = (tid & 1) * 16;    // 0 or 16
    const int wc = tid >> 2;          // 0..63 (c row for W load)
    const int wk = (tid & 3) * 8;     // 0,8,16,24

    for (int kc = 0; kc < 256; kc += KC) {
        const float4* ap = (const float4*)(A + lb * Tn + k0 + kc + lk);
#pragma unroll
        for (int q = 0; q < 4; q++) {
            float4 v = ap[q];
            As[lk + q * 4 + 0][lb] = v.x;
            As[lk + q * 4 + 1][lb] = v.y;
            As[lk + q * 4 + 2][lb] = v.z;
            As[lk + q * 4 + 3][lb] = v.w;
        }
        const float4* wp = (const float4*)(W + (c0 + wc) * Tn + k0 + kc + wk);
#pragma unroll
        for (int q = 0; q < 2; q++) {
            float4 v = wp[q];
            Ws[wk + q * 4 + 0][wc] = v.x;
            Ws[wk + q * 4 + 1][wc] = v.y;
            Ws[wk + q * 4 + 2][wc] = v.z;
            Ws[wk + q * 4 + 3][wc] = v.w;
        }
        __syncthreads();

#pragma unroll
        for (int kk = 0; kk < KC; kk++) {
            float a[8], wr[4];
            *(float4*)&a[0] = *(const float4*)&As[kk][ty * 8];
            *(float4*)&a[4] = *(const float4*)&As[kk][ty * 8 + 4];
            *(float4*)&wr[0] = *(const float4*)&Ws[kk][tx * 4];
#pragma unroll
            for (int i = 0; i < 8; i++)
#pragma unroll
                for (int j = 0; j < 4; j++)
                    acc[i][j] = fmaf(a[i], wr[j], acc[i][j]);
        }
        __syncthreads();
    }

#pragma unroll
    for (int i = 0; i < 8; i++) {
        int bb = ty * 8 + i;
#pragma unroll
        for (int j = 0; j < 4; j++)
            atomicAdd(&g_acc[bb * Cn + c0 + tx * 4 + j], acc[i][j]);
    }
}

// ---------------------------------------------------------------------------
// Kernel 3: bias + relu epilogue
// ---------------------------------------------------------------------------
__global__ __launch_bounds__(256) void epilogue_kernel(
    const float* __restrict__ bfv,
    const float* __restrict__ bft,
    float* __restrict__ out)
{
    int i = blockIdx.x * 256 + threadIdx.x;
    int c = i & (Cn - 1);
    float v = g_acc[i] + bfv[c] + bft[c];
    out[i] = v > 0.f ? v : 0.f;
}

// ---------------------------------------------------------------------------
extern "C" void kernel_launch(void* const* d_in, const int* in_sizes, int n_in,
                              void* d_out, int out_size)
{
    const float* vis    = (const float*)d_in[0];
    const float* txt    = (const float*)d_in[1];
    const float* w_vis  = (const float*)d_in[2];
    const float* w_text = (const float*)d_in[3];
    const float* bias   = (const float*)d_in[4];
    const float* Wfv    = (const float*)d_in[5];
    const float* bfv    = (const float*)d_in[6];
    const float* Wft    = (const float*)d_in[7];
    const float* bft    = (const float*)d_in[8];
    float* out = (float*)d_out;

    void* vs_ptr = nullptr;
    void* acc_ptr = nullptr;
    cudaGetSymbolAddress(&vs_ptr, g_vs);
    cudaGetSymbolAddress(&acc_ptr, g_acc);
    cudaMemsetAsync(vs_ptr, 0, Bn * Tn * sizeof(float));
    cudaMemsetAsync(acc_ptr, 0, Bn * Cn * sizeof(float));

    const int smem_bytes = (VT * Tn + Tn + Tn + VT) * (int)sizeof(float);  // 73792
    cudaFuncSetAttribute(attn_pass_kernel,
                         cudaFuncAttributeMaxDynamicSharedMemorySize, smem_bytes);

    dim3 g1(Vn / VT, Bn);
    attn_pass_kernel<<<g1, 256, smem_bytes>>>(vis, txt, w_vis, w_text, bias);

    dim3 g2(16, 8);
    gemm_split_kernel<<<g2, 256>>>(Wfv, Wft);

    epilogue_kernel<<<(Bn * Cn) / 256, 256>>>(bfv, bft, out);
}